// round 14
// baseline (speedup 1.0000x reference)
#include <cuda_runtime.h>
#include <cuda_fp16.h>
#include <math.h>
#include <stdint.h>

// Problem constants
#define BB 2
#define SS 4096
#define DD 768
#define HH 12
#define LL 4
#define WW 128
#define DFF 3072
#define DH 64
#define MM (BB*SS)          // 8192 rows
#define NC (SS/WW)          // 32 chunks

#define NEG_BIG (-1e30f)
#define M_CLAMP (-1e28f)

// ---------------- scratch buffers ----------------
__device__ float  g_x [MM*DD];
__device__ __half g_xh[MM*DD];           // fp16 activation stream (GEMM A)
__device__ __half g_qh[MM*DD];           // fp16 q (pre-scaled by 1/8), k, v
__device__ __half g_kh[MM*DD];
__device__ __half g_vh[MM*DD];
__device__ __half g_h1[MM*DFF];          // FFN intermediate, fp16
__device__ float  g_h2 [MM*DD];          // FFN2 split-K partial 0 (+bias)
__device__ float  g_h2b[MM*DD];          // FFN2 split-K partial 1
// fp16 weights, transposed to [N][K]
__device__ __half g_wq[LL*DD*DD];
__device__ __half g_wk[LL*DD*DD];
__device__ __half g_wv[LL*DD*DD];
__device__ __half g_w1[LL*DD*DFF];
__device__ __half g_w2[LL*DFF*DD];

// ---------------- helpers ----------------
__device__ __forceinline__ uint32_t smem_u32(const void* p) {
    uint32_t a;
    asm("{ .reg .u64 t; cvta.to.shared.u64 t, %1; cvt.u32.u64 %0, t; }"
        : "=r"(a) : "l"(p));
    return a;
}
__device__ __forceinline__ void cp16(uint32_t s, const void* g) {
    asm volatile("cp.async.cg.shared.global [%0], [%1], 16;" :: "r"(s), "l"(g));
}
__device__ __forceinline__ void mma16n8k16(float* c, const uint32_t* a, const uint32_t* b) {
    asm volatile(
        "mma.sync.aligned.m16n8k16.row.col.f32.f16.f16.f32 "
        "{%0,%1,%2,%3}, {%4,%5,%6,%7}, {%8,%9}, {%0,%1,%2,%3};"
        : "+f"(c[0]), "+f"(c[1]), "+f"(c[2]), "+f"(c[3])
        : "r"(a[0]), "r"(a[1]), "r"(a[2]), "r"(a[3]), "r"(b[0]), "r"(b[1]));
}
__device__ __forceinline__ void ldsm_x4(uint32_t* r, uint32_t addr) {
    asm volatile("ldmatrix.sync.aligned.m8n8.x4.shared.b16 {%0,%1,%2,%3}, [%4];"
        : "=r"(r[0]), "=r"(r[1]), "=r"(r[2]), "=r"(r[3]) : "r"(addr));
}
__device__ __forceinline__ uint32_t h2pack(float a, float b) {
    __half2 h = __floats2half2_rn(a, b);
    return *(uint32_t*)&h;
}

// ---------------- conversion passes ----------------
__global__ __launch_bounds__(256) void f32_to_f16_kernel(
    const float* __restrict__ in, __half* __restrict__ out, int n4)
{
    int i = blockIdx.x * 256 + threadIdx.x;
    if (i < n4) {
        float4 v = ((const float4*)in)[i];
        ((__half2*)out)[i*2]   = __floats2half2_rn(v.x, v.y);
        ((__half2*)out)[i*2+1] = __floats2half2_rn(v.z, v.w);
    }
}

// transpose + convert: in f32 [R][C] -> out f16 [C][R], batched over layers (z).
__global__ __launch_bounds__(256) void trans_f16_kernel(
    const float* __restrict__ in, __half* __restrict__ out, int R, int C)
{
    __shared__ float t[64][33];
    const size_t lo = (size_t)blockIdx.z * R * C;
    const int bx = blockIdx.x * 32;
    const int by = blockIdx.y * 64;
    const int tx = threadIdx.x & 31;
    const int ty = threadIdx.x >> 5;
    #pragma unroll
    for (int i = ty; i < 64; i += 8)
        t[i][tx] = in[lo + (size_t)(by + i) * C + bx + tx];
    __syncthreads();
    #pragma unroll
    for (int r = ty; r < 32; r += 8) {
        __half2 h = __floats2half2_rn(t[2*tx][r], t[2*tx + 1][r]);
        *(__half2*)(out + lo + (size_t)(bx + r) * R + by + 2*tx) = h;
    }
}

// ---------------- fp16 mma GEMM: C = A(Mx*)[Klen cols] @ Bt(Nx*)[Klen]^T + bias ----
// CTA tile 128x128, 128 threads (4 warps, warp tile 64x64), K-chunk 32 halves,
// 3-stage cp.async, ldmatrix fragment loads, 2 CTAs/SM.
// lda/ldb decoupled from Klen for split-K.
#define HPAD 40                     // halves per smem row (32 + 8)
#define A_STG (128*HPAD)
#define B_STG (128*HPAD)
#define GEMM_SMEM (3*(A_STG + B_STG)*2)   // 61440 B

template<bool RELU, bool OUTH>
__device__ __forceinline__ void gemm_body(
    const __half* __restrict__ A, const __half* __restrict__ Bt,
    const float* __restrict__ bias, float* __restrict__ Cf, __half* __restrict__ Ch,
    int N, int Klen, int lda, int ldb, int cn0, int tm, __half* smh, float oscale)
{
    const int tid  = threadIdx.x;
    const int lane = tid & 31;
    const int wid  = tid >> 5;       // 0..3
    const int wm   = wid & 1;
    const int wn   = wid >> 1;       // 0..1
    const int r4   = lane >> 2;
    const int t4   = lane & 3;

    const uint32_t sbase = smem_u32(smh);
    const __half* aG[4]; uint32_t aS[4];
    const __half* bG[4]; uint32_t bS[4];
    #pragma unroll
    for (int i = 0; i < 4; i++) {
        int id = tid + i*128;
        int row = id >> 2, kc = id & 3;
        aG[i] = A + (size_t)(tm*128 + row) * lda + kc*8;
        aS[i] = sbase + (uint32_t)(row*HPAD + kc*8) * 2u;
        bG[i] = Bt + (size_t)(cn0 + row) * ldb + kc*8;
        bS[i] = sbase + (uint32_t)(3*A_STG)*2u + (uint32_t)(row*HPAD + kc*8) * 2u;
    }

    auto issue = [&](int s, int c) {
        const uint32_t ao = (uint32_t)s * (A_STG*2);
        const uint32_t bo = (uint32_t)s * (B_STG*2);
        #pragma unroll
        for (int i = 0; i < 4; i++) {
            cp16(aS[i] + ao, aG[i] + c*32);
            cp16(bS[i] + bo, bG[i] + c*32);
        }
    };

    const int a_lrow = lane & 15;
    const int a_lk   = (lane >> 4) * 8;
    const int b_lrow = (lane & 7) + ((lane >> 4) << 3);
    const int b_lk   = ((lane >> 3) & 1) * 8;

    float acc[4][8][4];
    #pragma unroll
    for (int i = 0; i < 4; i++)
        #pragma unroll
        for (int j = 0; j < 8; j++)
            #pragma unroll
            for (int t = 0; t < 4; t++) acc[i][j][t] = 0.f;

    const int NCH = Klen >> 5;
    issue(0, 0); asm volatile("cp.async.commit_group;");
    issue(1, 1); asm volatile("cp.async.commit_group;");

    for (int c = 0; c < NCH; c++) {
        asm volatile("cp.async.wait_group 1;");
        __syncthreads();
        if (c + 2 < NCH) issue((c + 2) % 3, c + 2);
        asm volatile("cp.async.commit_group;");

        const uint32_t as = sbase + (uint32_t)(c % 3) * (A_STG*2);
        const uint32_t bs = sbase + (uint32_t)(3*A_STG)*2u + (uint32_t)(c % 3) * (B_STG*2);
        #pragma unroll
        for (int ks = 0; ks < 2; ks++) {
            const int k0 = ks * 16;
            uint32_t af[4][4], bf[8][2];
            #pragma unroll
            for (int mi = 0; mi < 4; mi++)
                ldsm_x4(af[mi], as + (uint32_t)((wm*64 + mi*16 + a_lrow)*HPAD + k0 + a_lk) * 2u);
            #pragma unroll
            for (int np = 0; np < 4; np++) {
                uint32_t t[4];
                ldsm_x4(t, bs + (uint32_t)((wn*64 + np*16 + b_lrow)*HPAD + k0 + b_lk) * 2u);
                bf[2*np][0] = t[0]; bf[2*np][1] = t[1];
                bf[2*np+1][0] = t[2]; bf[2*np+1][1] = t[3];
            }
            #pragma unroll
            for (int mi = 0; mi < 4; mi++)
                #pragma unroll
                for (int ni = 0; ni < 8; ni++)
                    mma16n8k16(acc[mi][ni], af[mi], bf[ni]);
        }
    }

    #pragma unroll
    for (int mi = 0; mi < 4; mi++) {
        const int row0 = tm*128 + wm*64 + mi*16 + r4;
        #pragma unroll
        for (int ni = 0; ni < 8; ni++) {
            const int col = cn0 + wn*64 + ni*8 + t4*2;
            const float b0 = bias ? bias[col] : 0.f;
            const float b1 = bias ? bias[col + 1] : 0.f;
            float2 v0, v1;
            v0.x = acc[mi][ni][0] + b0; v0.y = acc[mi][ni][1] + b1;
            v1.x = acc[mi][ni][2] + b0; v1.y = acc[mi][ni][3] + b1;
            if (RELU) {
                v0.x = fmaxf(v0.x, 0.f); v0.y = fmaxf(v0.y, 0.f);
                v1.x = fmaxf(v1.x, 0.f); v1.y = fmaxf(v1.y, 0.f);
            }
            if (OUTH) {
                v0.x *= oscale; v0.y *= oscale; v1.x *= oscale; v1.y *= oscale;
                *(__half2*)(Ch + (size_t)row0 * N + col)       = __floats2half2_rn(v0.x, v0.y);
                *(__half2*)(Ch + (size_t)(row0 + 8) * N + col) = __floats2half2_rn(v1.x, v1.y);
            } else {
                *(float2*)(Cf + (size_t)row0 * N + col)       = v0;
                *(float2*)(Cf + (size_t)(row0 + 8) * N + col) = v1;
            }
        }
    }
}

template<bool RELU, bool OUTH>
__global__ __launch_bounds__(128, 2) void gemm_f16(
    const __half* __restrict__ A, const __half* __restrict__ Bt,
    const float* __restrict__ bias, float* __restrict__ Cf, __half* __restrict__ Ch,
    int N, int K)
{
    extern __shared__ __half smh[];
    gemm_body<RELU, OUTH>(A, Bt, bias, Cf, Ch, N, K, K, K,
                          blockIdx.x * 128, blockIdx.y, smh, 1.0f);
}

// FFN2 split-K: z selects K-half; split 0 adds bias -> h2, split 1 -> h2b.
__global__ __launch_bounds__(128, 2) void gemm_f16_splitk(
    const __half* __restrict__ A, const __half* __restrict__ Bt,
    const float* __restrict__ bias, float* __restrict__ C0, float* __restrict__ C1,
    int N, int K)
{
    extern __shared__ __half smh[];
    const int z = blockIdx.z;
    const int kh = K / 2;
    gemm_body<false, false>(A + z * kh, Bt + z * kh,
                            z == 0 ? bias : nullptr,
                            z == 0 ? C0 : C1, nullptr,
                            N, kh, K, K, blockIdx.x * 128, blockIdx.y, smh, 1.0f);
}

__global__ __launch_bounds__(128, 2) void gemm_qkv(
    const __half* __restrict__ A,
    const __half* __restrict__ Bq, const __half* __restrict__ Bk, const __half* __restrict__ Bv,
    const float* __restrict__ biq, const float* __restrict__ bik, const float* __restrict__ biv,
    __half* __restrict__ Cq, __half* __restrict__ Ck, __half* __restrict__ Cv)
{
    extern __shared__ __half smh[];
    const int sel = blockIdx.x / 6;
    const int tn  = blockIdx.x % 6;
    const __half* B  = (sel == 0) ? Bq  : (sel == 1) ? Bk  : Bv;
    const float*  bi = (sel == 0) ? biq : (sel == 1) ? bik : biv;
    __half*       C  = (sel == 0) ? Cq  : (sel == 1) ? Ck  : Cv;
    const float   sc = (sel == 0) ? 0.125f : 1.0f;
    gemm_body<false, true>(A, B, bi, nullptr, C, DD, DD, DD, DD,
                           tn * 128, blockIdx.y, smh, sc);
}

// ---------------- tensor-core band attention (round-11 verified) ----------------
#define QP 72                       // halves per qs/ks row (64 + 8)
#define VP 136                      // halves per vt row (128 + 8)
#define ATTN_SMEM ((2*128*QP + 64*VP)*2)   // 54272 B

__global__ __launch_bounds__(256, 2) void band_attn_tc(
    const __half* __restrict__ q, const __half* __restrict__ k,
    const __half* __restrict__ v, const float* __restrict__ xin,
    float* __restrict__ xout, __half* __restrict__ xh)
{
    extern __shared__ __half sm[];
    __half* qs = sm;                  // 128 x QP
    __half* ks = sm + 128*QP;         // 128 x QP
    __half* vt = sm + 2*128*QP;       // 64 x VP (transposed V)

    const int c = blockIdx.x, h = blockIdx.y, b = blockIdx.z;
    const int tid  = threadIdx.x;
    const int lane = tid & 31;
    const int w    = tid >> 5;
    const int r4   = lane >> 2, t4 = lane & 3;
    const int wrow = w * 16;

    const uint32_t qsu = smem_u32(qs);
    const uint32_t ksu = smem_u32(ks);
    const uint32_t vtu = smem_u32(vt);

    const int a_lrow = lane & 15;
    const int a_lk   = (lane >> 4) * 8;
    const int b_lrow = (lane & 7) + ((lane >> 4) << 3);
    const int b_lk   = ((lane >> 3) & 1) * 8;

    // Q tile
    {
        const int row = tid >> 1, ch = (tid & 1) * 4;
        const __half* gq = q + (size_t)(b*SS + c*WW + row) * DD + h*DH + ch*8;
        const uint32_t ds = qsu + (uint32_t)(row*QP + ch*8) * 2u;
        #pragma unroll
        for (int i = 0; i < 4; i++) cp16(ds + i*16, gq + i*8);
    }
    asm volatile("cp.async.commit_group;");

    float Of[8][4];
    #pragma unroll
    for (int i = 0; i < 8; i++)
        #pragma unroll
        for (int j = 0; j < 4; j++) Of[i][j] = 0.f;
    float m0 = M_CLAMP, m1 = M_CLAMP, l0 = 0.f, l1 = 0.f;
    uint32_t qa[4][4];

    const int tbeg = (c == 0) ? 1 : 0;
    const int tend = (c == NC-1) ? 1 : 2;

    for (int t = tbeg; t <= tend; t++) {
        __syncthreads();
        // K tile
        {
            const int row = tid >> 1, ch = (tid & 1) * 4;
            const int jg = c*WW + t*128 - WW + row;
            const __half* gk = k + (size_t)(b*SS + jg) * DD + h*DH + ch*8;
            const uint32_t ds = ksu + (uint32_t)(row*QP + ch*8) * 2u;
            #pragma unroll
            for (int i = 0; i < 4; i++) cp16(ds + i*16, gk + i*8);
        }
        asm volatile("cp.async.commit_group;");
        // V tile -> transposed into vt[dim][key]
        {
            const int key = tid >> 1, d0 = (tid & 1) * 32;
            const int jg = c*WW + t*128 - WW + key;
            const __half* gv = v + (size_t)(b*SS + jg) * DD + h*DH + d0;
            #pragma unroll
            for (int i = 0; i < 4; i++) {
                uint4 u = *(const uint4*)(gv + i*8);
                const __half* hp = (const __half*)&u;
                #pragma unroll
                for (int d = 0; d < 8; d++)
                    vt[(d0 + i*8 + d)*VP + key] = hp[d];
            }
        }
        asm volatile("cp.async.wait_group 0;");
        __syncthreads();

        if (t == tbeg) {   // Q fragments, loaded once
            #pragma unroll
            for (int kk = 0; kk < 4; kk++)
                ldsm_x4(qa[kk], qsu + (uint32_t)((wrow + a_lrow)*QP + kk*16 + a_lk) * 2u);
        }

        // two halves of 64 keys each: chunked online softmax (S = 8 frags)
        #pragma unroll
        for (int half = 0; half < 2; half++) {
            const int kbase = half * 64;
            float S[8][4];
            #pragma unroll
            for (int j2 = 0; j2 < 4; j2++) {
                float* s0 = S[2*j2];
                float* s1 = S[2*j2+1];
                s0[0]=s0[1]=s0[2]=s0[3]=0.f;
                s1[0]=s1[1]=s1[2]=s1[3]=0.f;
                #pragma unroll
                for (int kk = 0; kk < 4; kk++) {
                    uint32_t bt[4];
                    ldsm_x4(bt, ksu + (uint32_t)((kbase + j2*16 + b_lrow)*QP + kk*16 + b_lk) * 2u);
                    mma16n8k16(s0, qa[kk], bt);
                    mma16n8k16(s1, qa[kk], bt + 2);
                }
            }

            // band mask
            if (t == 0) {
                #pragma unroll
                for (int j = 0; j < 8; j++) {
                    const int key0 = kbase + j*8 + t4*2;
                    const int q0 = wrow + r4, q1 = q0 + 8;
                    if (key0     < q0) S[j][0] = NEG_BIG;
                    if (key0 + 1 < q0) S[j][1] = NEG_BIG;
                    if (key0     < q1) S[j][2] = NEG_BIG;
                    if (key0 + 1 < q1) S[j][3] = NEG_BIG;
                }
            } else if (t == 2) {
                #pragma unroll
                for (int j = 0; j < 8; j++) {
                    const int key0 = kbase + j*8 + t4*2;
                    const int q0 = wrow + r4, q1 = q0 + 8;
                    if (key0     > q0) S[j][0] = NEG_BIG;
                    if (key0 + 1 > q0) S[j][1] = NEG_BIG;
                    if (key0     > q1) S[j][2] = NEG_BIG;
                    if (key0 + 1 > q1) S[j][3] = NEG_BIG;
                }
            }

            // row max, quad reduce; clamp handles fully-masked halves
            float mx0 = NEG_BIG, mx1 = NEG_BIG;
            #pragma unroll
            for (int j = 0; j < 8; j++) {
                mx0 = fmaxf(mx0, fmaxf(S[j][0], S[j][1]));
                mx1 = fmaxf(mx1, fmaxf(S[j][2], S[j][3]));
            }
            mx0 = fmaxf(mx0, __shfl_xor_sync(0xffffffffu, mx0, 1));
            mx0 = fmaxf(mx0, __shfl_xor_sync(0xffffffffu, mx0, 2));
            mx1 = fmaxf(mx1, __shfl_xor_sync(0xffffffffu, mx1, 1));
            mx1 = fmaxf(mx1, __shfl_xor_sync(0xffffffffu, mx1, 2));

            const float mn0 = fmaxf(fmaxf(m0, mx0), M_CLAMP);
            const float mn1 = fmaxf(fmaxf(m1, mx1), M_CLAMP);
            const float sc0 = __expf(m0 - mn0), sc1 = __expf(m1 - mn1);
            m0 = mn0; m1 = mn1;
            l0 *= sc0; l1 *= sc1;
            #pragma unroll
            for (int nf = 0; nf < 8; nf++) {
                Of[nf][0] *= sc0; Of[nf][1] *= sc0;
                Of[nf][2] *= sc1; Of[nf][3] *= sc1;
            }

            // exp -> P frags, then P @ V
            #pragma unroll
            for (int kk = 0; kk < 4; kk++) {
                const float p00 = __expf(S[2*kk][0]   - m0);
                const float p01 = __expf(S[2*kk][1]   - m0);
                const float p02 = __expf(S[2*kk][2]   - m1);
                const float p03 = __expf(S[2*kk][3]   - m1);
                const float p10 = __expf(S[2*kk+1][0] - m0);
                const float p11 = __expf(S[2*kk+1][1] - m0);
                const float p12 = __expf(S[2*kk+1][2] - m1);
                const float p13 = __expf(S[2*kk+1][3] - m1);
                l0 += p00 + p01 + p10 + p11;
                l1 += p02 + p03 + p12 + p13;
                uint32_t pa[4];
                pa[0] = h2pack(p00, p01);
                pa[1] = h2pack(p02, p03);
                pa[2] = h2pack(p10, p11);
                pa[3] = h2pack(p12, p13);
                #pragma unroll
                for (int np = 0; np < 4; np++) {
                    uint32_t bt[4];
                    ldsm_x4(bt, vtu + (uint32_t)((np*16 + b_lrow)*VP + kbase + kk*16 + b_lk) * 2u);
                    mma16n8k16(Of[2*np],   pa, bt);
                    mma16n8k16(Of[2*np+1], pa, bt + 2);
                }
            }
        }
    }

    // finalize
    l0 += __shfl_xor_sync(0xffffffffu, l0, 1);
    l0 += __shfl_xor_sync(0xffffffffu, l0, 2);
    l1 += __shfl_xor_sync(0xffffffffu, l1, 1);
    l1 += __shfl_xor_sync(0xffffffffu, l1, 2);
    const float inv0 = 1.0f / l0, inv1 = 1.0f / l1;

    const size_t rb0 = (size_t)(b*SS + c*WW + wrow + r4) * DD + h*DH;
    const size_t rb1 = rb0 + 8*DD;
    #pragma unroll
    for (int nf = 0; nf < 8; nf++) {
        const int col = nf*8 + t4*2;
        float2 o0, o1;
        o0.x = xin[rb0 + col]     + Of[nf][0] * inv0;
        o0.y = xin[rb0 + col + 1] + Of[nf][1] * inv0;
        o1.x = xin[rb1 + col]     + Of[nf][2] * inv1;
        o1.y = xin[rb1 + col + 1] + Of[nf][3] * inv1;
        *(float2*)(xout + rb0 + col) = o0;
        *(float2*)(xout + rb1 + col) = o1;
        *(__half2*)(xh + rb0 + col) = __floats2half2_rn(o0.x, o0.y);
        *(__half2*)(xh + rb1 + col) = __floats2half2_rn(o1.x, o1.y);
    }
}

// ---------------- fused add + LayerNorm (dual fp32/fp16 output) ----------------
__device__ __forceinline__ float block_sum_256(float v, float* red) {
    int lane = threadIdx.x & 31;
    #pragma unroll
    for (int o = 16; o > 0; o >>= 1) v += __shfl_xor_sync(0xffffffffu, v, o);
    if (lane == 0) red[threadIdx.x >> 5] = v;
    __syncthreads();
    float r = (threadIdx.x < 8) ? red[threadIdx.x] : 0.f;
    if ((threadIdx.x >> 5) == 0) {
        #pragma unroll
        for (int o = 16; o > 0; o >>= 1) r += __shfl_xor_sync(0xffffffffu, r, o);
        if (lane == 0) red[0] = r;
    }
    __syncthreads();
    r = red[0];
    __syncthreads();
    return r;
}

__global__ __launch_bounds__(256) void add_ln_kernel(
    const float* __restrict__ x, const float* __restrict__ hh,
    const float* __restrict__ hh2,
    const float* __restrict__ g, const float* __restrict__ bta,
    float* __restrict__ out, __half* __restrict__ outh)
{
    __shared__ float red[8];
    const int row = blockIdx.x;
    const size_t base = (size_t)row * DD;
    const int t = threadIdx.x;

    float vals[3];
    float s = 0.f;
    #pragma unroll
    for (int i = 0; i < 3; i++) {
        int idx = t + i * 256;
        float vv = x[base + idx];
        if (hh)  vv += hh[base + idx];
        if (hh2) vv += hh2[base + idx];
        vals[i] = vv;
        s += vv;
    }
    float total = block_sum_256(s, red);
    float mu = total * (1.0f / DD);

    float vsum = 0.f;
    #pragma unroll
    for (int i = 0; i < 3; i++) {
        float d = vals[i] - mu;
        vsum += d * d;
    }
    float vtot = block_sum_256(vsum, red);
    float rstd = rsqrtf(vtot * (1.0f / DD) + 1e-6f);

    #pragma unroll
    for (int i = 0; i < 3; i++) {
        int idx = t + i * 256;
        float o = (vals[i] - mu) * rstd * g[idx] + bta[idx];
        out[base + idx] = o;
        if (outh) outh[base + idx] = __float2half(o);
    }
}

// ---------------- launcher ----------------
extern "C" void kernel_launch(void* const* d_in, const int* in_sizes, int n_in,
                              void* d_out, int out_size)
{
    const float* src   = (const float*)d_in[0];
    const float* Wq    = (const float*)d_in[1];
    const float* bq    = (const float*)d_in[2];
    const float* Wk    = (const float*)d_in[3];
    const float* bk    = (const float*)d_in[4];
    const float* Wv    = (const float*)d_in[5];
    const float* bv    = (const float*)d_in[6];
    const float* W1    = (const float*)d_in[7];
    const float* b1    = (const float*)d_in[8];
    const float* W2    = (const float*)d_in[9];
    const float* b2    = (const float*)d_in[10];
    const float* ln2_g = (const float*)d_in[11];
    const float* ln2_b = (const float*)d_in[12];
    const float* lnf_g = (const float*)d_in[13];
    const float* lnf_b = (const float*)d_in[14];

    float *x, *h2, *h2b;
    __half *xh, *qh, *kh, *vh, *h1, *wq, *wk, *wv, *w1, *w2;
    cudaGetSymbolAddress((void**)&x,   g_x);
    cudaGetSymbolAddress((void**)&xh,  g_xh);
    cudaGetSymbolAddress((void**)&qh,  g_qh);
    cudaGetSymbolAddress((void**)&kh,  g_kh);
    cudaGetSymbolAddress((void**)&vh,  g_vh);
    cudaGetSymbolAddress((void**)&h1,  g_h1);
    cudaGetSymbolAddress((void**)&h2,  g_h2);
    cudaGetSymbolAddress((void**)&h2b, g_h2b);
    cudaGetSymbolAddress((void**)&wq,  g_wq);
    cudaGetSymbolAddress((void**)&wk,  g_wk);
    cudaGetSymbolAddress((void**)&wv,  g_wv);
    cudaGetSymbolAddress((void**)&w1,  g_w1);
    cudaGetSymbolAddress((void**)&w2,  g_w2);

    cudaFuncSetAttribute(band_attn_tc,
                         cudaFuncAttributeMaxDynamicSharedMemorySize, ATTN_SMEM);
    cudaFuncSetAttribute(gemm_f16<true,true>,
                         cudaFuncAttributeMaxDynamicSharedMemorySize, GEMM_SMEM);
    cudaFuncSetAttribute(gemm_f16<false,false>,
                         cudaFuncAttributeMaxDynamicSharedMemorySize, GEMM_SMEM);
    cudaFuncSetAttribute(gemm_f16_splitk,
                         cudaFuncAttributeMaxDynamicSharedMemorySize, GEMM_SMEM);
    cudaFuncSetAttribute(gemm_qkv,
                         cudaFuncAttributeMaxDynamicSharedMemorySize, GEMM_SMEM);

    // weight transpose+convert to fp16 [N][K], batched over layers
    {
        dim3 blk(256);
        trans_f16_kernel<<<dim3(DD/32, DD/64, LL), blk>>>(Wq, wq, DD, DD);
        trans_f16_kernel<<<dim3(DD/32, DD/64, LL), blk>>>(Wk, wk, DD, DD);
        trans_f16_kernel<<<dim3(DD/32, DD/64, LL), blk>>>(Wv, wv, DD, DD);
        trans_f16_kernel<<<dim3(DFF/32, DD/64, LL), blk>>>(W1, w1, DD, DFF);
        trans_f16_kernel<<<dim3(DD/32, DFF/64, LL), blk>>>(W2, w2, DFF, DD);
    }

    // src -> fp16 for layer-0 QKV
    f32_to_f16_kernel<<<(MM*DD/4 + 255)/256, 256>>>(src, xh, MM*DD/4);

    dim3 gQKV(18, MM/128);          // 3 x (768/128) n-tiles
    dim3 gF1(DFF/128, MM/128);      // (24, 64)
    dim3 gF2(DD/128, MM/128, 2);    // (6, 64, 2) split-K: 768 CTAs
    dim3 gA(NC, HH, BB);

    for (int i = 0; i < LL; i++) {
        const float* xin = (i == 0) ? src : x;

        gemm_qkv<<<gQKV, 128, GEMM_SMEM>>>(xh,
            wq + (size_t)i*DD*DD, wk + (size_t)i*DD*DD, wv + (size_t)i*DD*DD,
            bq + i*DD, bk + i*DD, bv + i*DD, qh, kh, vh);

        band_attn_tc<<<gA, 256, ATTN_SMEM>>>(qh, kh, vh, xin, x, xh);

        gemm_f16<true,true><<<gF1, 128, GEMM_SMEM>>>(
            xh, w1 + (size_t)i*DD*DFF, b1 + i*DFF, nullptr, h1, DFF, DD);
        gemm_f16_splitk<<<gF2, 128, GEMM_SMEM>>>(
            h1, w2 + (size_t)i*DFF*DD, b2 + i*DD, h2, h2b, DD, DFF);

        add_ln_kernel<<<MM, 256>>>(x, h2, h2b, ln2_g + i*DD, ln2_b + i*DD, x, xh);
    }

    add_ln_kernel<<<MM, 256>>>(x, nullptr, nullptr, lnf_g, lnf_b, (float*)d_out, nullptr);
}

// round 15
// speedup vs baseline: 1.5247x; 1.5247x over previous
#include <cuda_runtime.h>
#include <cuda_fp16.h>
#include <math.h>
#include <stdint.h>

// Problem constants
#define BB 2
#define SS 4096
#define DD 768
#define HH 12
#define LL 4
#define WW 128
#define DFF 3072
#define DH 64
#define MM (BB*SS)          // 8192 rows
#define NC (SS/WW)          // 32 chunks

#define NEG_BIG (-1e30f)
#define M_CLAMP (-1e28f)

// ---------------- scratch buffers ----------------
__device__ float  g_x [MM*DD];
__device__ __half g_xh[MM*DD];           // fp16 activation stream (GEMM A)
__device__ __half g_qh[MM*DD];           // fp16 q (pre-scaled by 1/8), k, v
__device__ __half g_kh[MM*DD];
__device__ __half g_vh[MM*DD];
__device__ __half g_h1[MM*DFF];          // FFN intermediate, fp16
__device__ float  g_h2 [MM*DD];          // FFN2 split-K partial 0 (+bias)
__device__ float  g_h2b[MM*DD];          // FFN2 split-K partial 1
__device__ float  g_zero[DD];            // zero bias (static-zeroed)
// fp16 weights, transposed to [N][K]
__device__ __half g_wq[LL*DD*DD];
__device__ __half g_wk[LL*DD*DD];
__device__ __half g_wv[LL*DD*DD];
__device__ __half g_w1[LL*DD*DFF];
__device__ __half g_w2[LL*DFF*DD];

// ---------------- helpers ----------------
__device__ __forceinline__ uint32_t smem_u32(const void* p) {
    uint32_t a;
    asm("{ .reg .u64 t; cvta.to.shared.u64 t, %1; cvt.u32.u64 %0, t; }"
        : "=r"(a) : "l"(p));
    return a;
}
__device__ __forceinline__ void cp16(uint32_t s, const void* g) {
    asm volatile("cp.async.cg.shared.global [%0], [%1], 16;" :: "r"(s), "l"(g));
}
__device__ __forceinline__ void mma16n8k16(float* c, const uint32_t* a, const uint32_t* b) {
    asm volatile(
        "mma.sync.aligned.m16n8k16.row.col.f32.f16.f16.f32 "
        "{%0,%1,%2,%3}, {%4,%5,%6,%7}, {%8,%9}, {%0,%1,%2,%3};"
        : "+f"(c[0]), "+f"(c[1]), "+f"(c[2]), "+f"(c[3])
        : "r"(a[0]), "r"(a[1]), "r"(a[2]), "r"(a[3]), "r"(b[0]), "r"(b[1]));
}
__device__ __forceinline__ void ldsm_x4(uint32_t* r, uint32_t addr) {
    asm volatile("ldmatrix.sync.aligned.m8n8.x4.shared.b16 {%0,%1,%2,%3}, [%4];"
        : "=r"(r[0]), "=r"(r[1]), "=r"(r[2]), "=r"(r[3]) : "r"(addr));
}
__device__ __forceinline__ uint32_t h2pack(float a, float b) {
    __half2 h = __floats2half2_rn(a, b);
    return *(uint32_t*)&h;
}

// ---------------- conversion passes ----------------
__global__ __launch_bounds__(256) void f32_to_f16_kernel(
    const float* __restrict__ in, __half* __restrict__ out, int n4)
{
    int i = blockIdx.x * 256 + threadIdx.x;
    if (i < n4) {
        float4 v = ((const float4*)in)[i];
        ((__half2*)out)[i*2]   = __floats2half2_rn(v.x, v.y);
        ((__half2*)out)[i*2+1] = __floats2half2_rn(v.z, v.w);
    }
}

// transpose + convert: in f32 [R][C] -> out f16 [C][R], batched over layers (z).
__global__ __launch_bounds__(256) void trans_f16_kernel(
    const float* __restrict__ in, __half* __restrict__ out, int R, int C)
{
    __shared__ float t[64][33];
    const size_t lo = (size_t)blockIdx.z * R * C;
    const int bx = blockIdx.x * 32;
    const int by = blockIdx.y * 64;
    const int tx = threadIdx.x & 31;
    const int ty = threadIdx.x >> 5;
    #pragma unroll
    for (int i = ty; i < 64; i += 8)
        t[i][tx] = in[lo + (size_t)(by + i) * C + bx + tx];
    __syncthreads();
    #pragma unroll
    for (int r = ty; r < 32; r += 8) {
        __half2 h = __floats2half2_rn(t[2*tx][r], t[2*tx + 1][r]);
        *(__half2*)(out + lo + (size_t)(bx + r) * R + by + 2*tx) = h;
    }
}

// ---------------- fp16 mma GEMM: C = A(MxK) @ Bt(NxK)^T + bias ----------------
// (round-11 verified body, untouched)
// CTA tile 128x128, 128 threads (4 warps, warp tile 64x64), K-chunk 32 halves,
// 3-stage cp.async, ldmatrix fragment loads, 2 CTAs/SM.
#define HPAD 40                     // halves per smem row (32 + 8)
#define A_STG (128*HPAD)
#define B_STG (128*HPAD)
#define GEMM_SMEM (3*(A_STG + B_STG)*2)   // 61440 B

template<bool RELU, bool OUTH>
__device__ __forceinline__ void gemm_body(
    const __half* __restrict__ A, const __half* __restrict__ Bt,
    const float* __restrict__ bias, float* __restrict__ Cf, __half* __restrict__ Ch,
    int N, int K, int cn0, int tm, __half* smh, float oscale)
{
    const int tid  = threadIdx.x;
    const int lane = tid & 31;
    const int wid  = tid >> 5;       // 0..3
    const int wm   = wid & 1;
    const int wn   = wid >> 1;       // 0..1
    const int r4   = lane >> 2;
    const int t4   = lane & 3;

    const uint32_t sbase = smem_u32(smh);
    const __half* aG[4]; uint32_t aS[4];
    const __half* bG[4]; uint32_t bS[4];
    #pragma unroll
    for (int i = 0; i < 4; i++) {
        int id = tid + i*128;
        int row = id >> 2, kc = id & 3;
        aG[i] = A + (size_t)(tm*128 + row) * K + kc*8;
        aS[i] = sbase + (uint32_t)(row*HPAD + kc*8) * 2u;
        bG[i] = Bt + (size_t)(cn0 + row) * K + kc*8;
        bS[i] = sbase + (uint32_t)(3*A_STG)*2u + (uint32_t)(row*HPAD + kc*8) * 2u;
    }

    auto issue = [&](int s, int c) {
        const uint32_t ao = (uint32_t)s * (A_STG*2);
        const uint32_t bo = (uint32_t)s * (B_STG*2);
        #pragma unroll
        for (int i = 0; i < 4; i++) {
            cp16(aS[i] + ao, aG[i] + c*32);
            cp16(bS[i] + bo, bG[i] + c*32);
        }
    };

    const int a_lrow = lane & 15;
    const int a_lk   = (lane >> 4) * 8;
    const int b_lrow = (lane & 7) + ((lane >> 4) << 3);
    const int b_lk   = ((lane >> 3) & 1) * 8;

    float acc[4][8][4];
    #pragma unroll
    for (int i = 0; i < 4; i++)
        #pragma unroll
        for (int j = 0; j < 8; j++)
            #pragma unroll
            for (int t = 0; t < 4; t++) acc[i][j][t] = 0.f;

    const int NCH = K >> 5;
    issue(0, 0); asm volatile("cp.async.commit_group;");
    issue(1, 1); asm volatile("cp.async.commit_group;");

    for (int c = 0; c < NCH; c++) {
        asm volatile("cp.async.wait_group 1;");
        __syncthreads();
        if (c + 2 < NCH) issue((c + 2) % 3, c + 2);
        asm volatile("cp.async.commit_group;");

        const uint32_t as = sbase + (uint32_t)(c % 3) * (A_STG*2);
        const uint32_t bs = sbase + (uint32_t)(3*A_STG)*2u + (uint32_t)(c % 3) * (B_STG*2);
        #pragma unroll
        for (int ks = 0; ks < 2; ks++) {
            const int k0 = ks * 16;
            uint32_t af[4][4], bf[8][2];
            #pragma unroll
            for (int mi = 0; mi < 4; mi++)
                ldsm_x4(af[mi], as + (uint32_t)((wm*64 + mi*16 + a_lrow)*HPAD + k0 + a_lk) * 2u);
            #pragma unroll
            for (int np = 0; np < 4; np++) {
                uint32_t t[4];
                ldsm_x4(t, bs + (uint32_t)((wn*64 + np*16 + b_lrow)*HPAD + k0 + b_lk) * 2u);
                bf[2*np][0] = t[0]; bf[2*np][1] = t[1];
                bf[2*np+1][0] = t[2]; bf[2*np+1][1] = t[3];
            }
            #pragma unroll
            for (int mi = 0; mi < 4; mi++)
                #pragma unroll
                for (int ni = 0; ni < 8; ni++)
                    mma16n8k16(acc[mi][ni], af[mi], bf[ni]);
        }
    }

    #pragma unroll
    for (int mi = 0; mi < 4; mi++) {
        const int row0 = tm*128 + wm*64 + mi*16 + r4;
        #pragma unroll
        for (int ni = 0; ni < 8; ni++) {
            const int col = cn0 + wn*64 + ni*8 + t4*2;
            const float b0 = bias[col], b1 = bias[col + 1];
            float2 v0, v1;
            v0.x = acc[mi][ni][0] + b0; v0.y = acc[mi][ni][1] + b1;
            v1.x = acc[mi][ni][2] + b0; v1.y = acc[mi][ni][3] + b1;
            if (RELU) {
                v0.x = fmaxf(v0.x, 0.f); v0.y = fmaxf(v0.y, 0.f);
                v1.x = fmaxf(v1.x, 0.f); v1.y = fmaxf(v1.y, 0.f);
            }
            if (OUTH) {
                v0.x *= oscale; v0.y *= oscale; v1.x *= oscale; v1.y *= oscale;
                *(__half2*)(Ch + (size_t)row0 * N + col)       = __floats2half2_rn(v0.x, v0.y);
                *(__half2*)(Ch + (size_t)(row0 + 8) * N + col) = __floats2half2_rn(v1.x, v1.y);
            } else {
                *(float2*)(Cf + (size_t)row0 * N + col)       = v0;
                *(float2*)(Cf + (size_t)(row0 + 8) * N + col) = v1;
            }
        }
    }
}

template<bool RELU, bool OUTH>
__global__ __launch_bounds__(128, 2) void gemm_f16(
    const __half* __restrict__ A, const __half* __restrict__ Bt,
    const float* __restrict__ bias, float* __restrict__ Cf, __half* __restrict__ Ch,
    int N, int K)
{
    extern __shared__ __half smh[];
    gemm_body<RELU, OUTH>(A, Bt, bias, Cf, Ch, N, K, blockIdx.x * 128, blockIdx.y, smh, 1.0f);
}

__global__ __launch_bounds__(128, 2) void gemm_qkv(
    const __half* __restrict__ A,
    const __half* __restrict__ Bq, const __half* __restrict__ Bk, const __half* __restrict__ Bv,
    const float* __restrict__ biq, const float* __restrict__ bik, const float* __restrict__ biv,
    __half* __restrict__ Cq, __half* __restrict__ Ck, __half* __restrict__ Cv)
{
    extern __shared__ __half smh[];
    const int sel = blockIdx.x / 6;
    const int tn  = blockIdx.x % 6;
    const __half* B  = (sel == 0) ? Bq  : (sel == 1) ? Bk  : Bv;
    const float*  bi = (sel == 0) ? biq : (sel == 1) ? bik : biv;
    __half*       C  = (sel == 0) ? Cq  : (sel == 1) ? Ck  : Cv;
    const float   sc = (sel == 0) ? 0.125f : 1.0f;
    gemm_body<false, true>(A, B, bi, nullptr, C, DD, DD, tn * 128, blockIdx.y, smh, sc);
}

// ---------------- FFN2 split-K: dedicated body, all constants compile-time ----------
// C_z = A[:, z*1536 : (z+1)*1536] @ W2t[:, same]^T  (+bias for z=0 via real bias,
// z=1 via zero buffer). Row strides fixed at 3072; Klen fixed at 1536.
__device__ __forceinline__ void gemm_body_sk(
    const __half* __restrict__ A, const __half* __restrict__ Bt,
    const float* __restrict__ bias, float* __restrict__ Cf,
    int cn0, int tm, __half* smh)
{
    constexpr int KLEN = DFF / 2;    // 1536
    constexpr int LD   = DFF;        // 3072
    constexpr int N    = DD;         // 768

    const int tid  = threadIdx.x;
    const int lane = tid & 31;
    const int wid  = tid >> 5;
    const int wm   = wid & 1;
    const int wn   = wid >> 1;
    const int r4   = lane >> 2;
    const int t4   = lane & 3;

    const uint32_t sbase = smem_u32(smh);
    const __half* aG[4]; uint32_t aS[4];
    const __half* bG[4]; uint32_t bS[4];
    #pragma unroll
    for (int i = 0; i < 4; i++) {
        int id = tid + i*128;
        int row = id >> 2, kc = id & 3;
        aG[i] = A + (size_t)(tm*128 + row) * LD + kc*8;
        aS[i] = sbase + (uint32_t)(row*HPAD + kc*8) * 2u;
        bG[i] = Bt + (size_t)(cn0 + row) * LD + kc*8;
        bS[i] = sbase + (uint32_t)(3*A_STG)*2u + (uint32_t)(row*HPAD + kc*8) * 2u;
    }

    auto issue = [&](int s, int c) {
        const uint32_t ao = (uint32_t)s * (A_STG*2);
        const uint32_t bo = (uint32_t)s * (B_STG*2);
        #pragma unroll
        for (int i = 0; i < 4; i++) {
            cp16(aS[i] + ao, aG[i] + c*32);
            cp16(bS[i] + bo, bG[i] + c*32);
        }
    };

    const int a_lrow = lane & 15;
    const int a_lk   = (lane >> 4) * 8;
    const int b_lrow = (lane & 7) + ((lane >> 4) << 3);
    const int b_lk   = ((lane >> 3) & 1) * 8;

    float acc[4][8][4];
    #pragma unroll
    for (int i = 0; i < 4; i++)
        #pragma unroll
        for (int j = 0; j < 8; j++)
            #pragma unroll
            for (int t = 0; t < 4; t++) acc[i][j][t] = 0.f;

    constexpr int NCH = KLEN >> 5;   // 48
    issue(0, 0); asm volatile("cp.async.commit_group;");
    issue(1, 1); asm volatile("cp.async.commit_group;");

    for (int c = 0; c < NCH; c++) {
        asm volatile("cp.async.wait_group 1;");
        __syncthreads();
        if (c + 2 < NCH) issue((c + 2) % 3, c + 2);
        asm volatile("cp.async.commit_group;");

        const uint32_t as = sbase + (uint32_t)(c % 3) * (A_STG*2);
        const uint32_t bs = sbase + (uint32_t)(3*A_STG)*2u + (uint32_t)(c % 3) * (B_STG*2);
        #pragma unroll
        for (int ks = 0; ks < 2; ks++) {
            const int k0 = ks * 16;
            uint32_t af[4][4], bf[8][2];
            #pragma unroll
            for (int mi = 0; mi < 4; mi++)
                ldsm_x4(af[mi], as + (uint32_t)((wm*64 + mi*16 + a_lrow)*HPAD + k0 + a_lk) * 2u);
            #pragma unroll
            for (int np = 0; np < 4; np++) {
                uint32_t t[4];
                ldsm_x4(t, bs + (uint32_t)((wn*64 + np*16 + b_lrow)*HPAD + k0 + b_lk) * 2u);
                bf[2*np][0] = t[0]; bf[2*np][1] = t[1];
                bf[2*np+1][0] = t[2]; bf[2*np+1][1] = t[3];
            }
            #pragma unroll
            for (int mi = 0; mi < 4; mi++)
                #pragma unroll
                for (int ni = 0; ni < 8; ni++)
                    mma16n8k16(acc[mi][ni], af[mi], bf[ni]);
        }
    }

    #pragma unroll
    for (int mi = 0; mi < 4; mi++) {
        const int row0 = tm*128 + wm*64 + mi*16 + r4;
        #pragma unroll
        for (int ni = 0; ni < 8; ni++) {
            const int col = cn0 + wn*64 + ni*8 + t4*2;
            const float b0 = bias[col], b1 = bias[col + 1];
            float2 v0, v1;
            v0.x = acc[mi][ni][0] + b0; v0.y = acc[mi][ni][1] + b1;
            v1.x = acc[mi][ni][2] + b0; v1.y = acc[mi][ni][3] + b1;
            *(float2*)(Cf + (size_t)row0 * N + col)       = v0;
            *(float2*)(Cf + (size_t)(row0 + 8) * N + col) = v1;
        }
    }
}

__global__ __launch_bounds__(128, 2) void gemm_ffn2_sk(
    const __half* __restrict__ A, const __half* __restrict__ Bt,
    const float* __restrict__ bias, const float* __restrict__ zbias,
    float* __restrict__ C0, float* __restrict__ C1)
{
    extern __shared__ __half smh[];
    const int z = blockIdx.z;
    gemm_body_sk(A + z * (DFF/2), Bt + z * (DFF/2),
                 z ? zbias : bias, z ? C1 : C0,
                 blockIdx.x * 128, blockIdx.y, smh);
}

// ---------------- tensor-core band attention (round-11 verified) ----------------
#define QP 72                       // halves per qs/ks row (64 + 8)
#define VP 136                      // halves per vt row (128 + 8)
#define ATTN_SMEM ((2*128*QP + 64*VP)*2)   // 54272 B

__global__ __launch_bounds__(256, 2) void band_attn_tc(
    const __half* __restrict__ q, const __half* __restrict__ k,
    const __half* __restrict__ v, const float* __restrict__ xin,
    float* __restrict__ xout, __half* __restrict__ xh)
{
    extern __shared__ __half sm[];
    __half* qs = sm;                  // 128 x QP
    __half* ks = sm + 128*QP;         // 128 x QP
    __half* vt = sm + 2*128*QP;       // 64 x VP (transposed V)

    const int c = blockIdx.x, h = blockIdx.y, b = blockIdx.z;
    const int tid  = threadIdx.x;
    const int lane = tid & 31;
    const int w    = tid >> 5;
    const int r4   = lane >> 2, t4 = lane & 3;
    const int wrow = w * 16;

    const uint32_t qsu = smem_u32(qs);
    const uint32_t ksu = smem_u32(ks);
    const uint32_t vtu = smem_u32(vt);

    const int a_lrow = lane & 15;
    const int a_lk   = (lane >> 4) * 8;
    const int b_lrow = (lane & 7) + ((lane >> 4) << 3);
    const int b_lk   = ((lane >> 3) & 1) * 8;

    // Q tile
    {
        const int row = tid >> 1, ch = (tid & 1) * 4;
        const __half* gq = q + (size_t)(b*SS + c*WW + row) * DD + h*DH + ch*8;
        const uint32_t ds = qsu + (uint32_t)(row*QP + ch*8) * 2u;
        #pragma unroll
        for (int i = 0; i < 4; i++) cp16(ds + i*16, gq + i*8);
    }
    asm volatile("cp.async.commit_group;");

    float Of[8][4];
    #pragma unroll
    for (int i = 0; i < 8; i++)
        #pragma unroll
        for (int j = 0; j < 4; j++) Of[i][j] = 0.f;
    float m0 = M_CLAMP, m1 = M_CLAMP, l0 = 0.f, l1 = 0.f;
    uint32_t qa[4][4];

    const int tbeg = (c == 0) ? 1 : 0;
    const int tend = (c == NC-1) ? 1 : 2;

    for (int t = tbeg; t <= tend; t++) {
        __syncthreads();
        // K tile
        {
            const int row = tid >> 1, ch = (tid & 1) * 4;
            const int jg = c*WW + t*128 - WW + row;
            const __half* gk = k + (size_t)(b*SS + jg) * DD + h*DH + ch*8;
            const uint32_t ds = ksu + (uint32_t)(row*QP + ch*8) * 2u;
            #pragma unroll
            for (int i = 0; i < 4; i++) cp16(ds + i*16, gk + i*8);
        }
        asm volatile("cp.async.commit_group;");
        // V tile -> transposed into vt[dim][key]
        {
            const int key = tid >> 1, d0 = (tid & 1) * 32;
            const int jg = c*WW + t*128 - WW + key;
            const __half* gv = v + (size_t)(b*SS + jg) * DD + h*DH + d0;
            #pragma unroll
            for (int i = 0; i < 4; i++) {
                uint4 u = *(const uint4*)(gv + i*8);
                const __half* hp = (const __half*)&u;
                #pragma unroll
                for (int d = 0; d < 8; d++)
                    vt[(d0 + i*8 + d)*VP + key] = hp[d];
            }
        }
        asm volatile("cp.async.wait_group 0;");
        __syncthreads();

        if (t == tbeg) {   // Q fragments, loaded once
            #pragma unroll
            for (int kk = 0; kk < 4; kk++)
                ldsm_x4(qa[kk], qsu + (uint32_t)((wrow + a_lrow)*QP + kk*16 + a_lk) * 2u);
        }

        // two halves of 64 keys each: chunked online softmax (S = 8 frags)
        #pragma unroll
        for (int half = 0; half < 2; half++) {
            const int kbase = half * 64;
            float S[8][4];
            #pragma unroll
            for (int j2 = 0; j2 < 4; j2++) {
                float* s0 = S[2*j2];
                float* s1 = S[2*j2+1];
                s0[0]=s0[1]=s0[2]=s0[3]=0.f;
                s1[0]=s1[1]=s1[2]=s1[3]=0.f;
                #pragma unroll
                for (int kk = 0; kk < 4; kk++) {
                    uint32_t bt[4];
                    ldsm_x4(bt, ksu + (uint32_t)((kbase + j2*16 + b_lrow)*QP + kk*16 + b_lk) * 2u);
                    mma16n8k16(s0, qa[kk], bt);
                    mma16n8k16(s1, qa[kk], bt + 2);
                }
            }

            // band mask
            if (t == 0) {
                #pragma unroll
                for (int j = 0; j < 8; j++) {
                    const int key0 = kbase + j*8 + t4*2;
                    const int q0 = wrow + r4, q1 = q0 + 8;
                    if (key0     < q0) S[j][0] = NEG_BIG;
                    if (key0 + 1 < q0) S[j][1] = NEG_BIG;
                    if (key0     < q1) S[j][2] = NEG_BIG;
                    if (key0 + 1 < q1) S[j][3] = NEG_BIG;
                }
            } else if (t == 2) {
                #pragma unroll
                for (int j = 0; j < 8; j++) {
                    const int key0 = kbase + j*8 + t4*2;
                    const int q0 = wrow + r4, q1 = q0 + 8;
                    if (key0     > q0) S[j][0] = NEG_BIG;
                    if (key0 + 1 > q0) S[j][1] = NEG_BIG;
                    if (key0     > q1) S[j][2] = NEG_BIG;
                    if (key0 + 1 > q1) S[j][3] = NEG_BIG;
                }
            }

            // row max, quad reduce; clamp handles fully-masked halves
            float mx0 = NEG_BIG, mx1 = NEG_BIG;
            #pragma unroll
            for (int j = 0; j < 8; j++) {
                mx0 = fmaxf(mx0, fmaxf(S[j][0], S[j][1]));
                mx1 = fmaxf(mx1, fmaxf(S[j][2], S[j][3]));
            }
            mx0 = fmaxf(mx0, __shfl_xor_sync(0xffffffffu, mx0, 1));
            mx0 = fmaxf(mx0, __shfl_xor_sync(0xffffffffu, mx0, 2));
            mx1 = fmaxf(mx1, __shfl_xor_sync(0xffffffffu, mx1, 1));
            mx1 = fmaxf(mx1, __shfl_xor_sync(0xffffffffu, mx1, 2));

            const float mn0 = fmaxf(fmaxf(m0, mx0), M_CLAMP);
            const float mn1 = fmaxf(fmaxf(m1, mx1), M_CLAMP);
            const float sc0 = __expf(m0 - mn0), sc1 = __expf(m1 - mn1);
            m0 = mn0; m1 = mn1;
            l0 *= sc0; l1 *= sc1;
            #pragma unroll
            for (int nf = 0; nf < 8; nf++) {
                Of[nf][0] *= sc0; Of[nf][1] *= sc0;
                Of[nf][2] *= sc1; Of[nf][3] *= sc1;
            }

            // exp -> P frags, then P @ V
            #pragma unroll
            for (int kk = 0; kk < 4; kk++) {
                const float p00 = __expf(S[2*kk][0]   - m0);
                const float p01 = __expf(S[2*kk][1]   - m0);
                const float p02 = __expf(S[2*kk][2]   - m1);
                const float p03 = __expf(S[2*kk][3]   - m1);
                const float p10 = __expf(S[2*kk+1][0] - m0);
                const float p11 = __expf(S[2*kk+1][1] - m0);
                const float p12 = __expf(S[2*kk+1][2] - m1);
                const float p13 = __expf(S[2*kk+1][3] - m1);
                l0 += p00 + p01 + p10 + p11;
                l1 += p02 + p03 + p12 + p13;
                uint32_t pa[4];
                pa[0] = h2pack(p00, p01);
                pa[1] = h2pack(p02, p03);
                pa[2] = h2pack(p10, p11);
                pa[3] = h2pack(p12, p13);
                #pragma unroll
                for (int np = 0; np < 4; np++) {
                    uint32_t bt[4];
                    ldsm_x4(bt, vtu + (uint32_t)((np*16 + b_lrow)*VP + kbase + kk*16 + b_lk) * 2u);
                    mma16n8k16(Of[2*np],   pa, bt);
                    mma16n8k16(Of[2*np+1], pa, bt + 2);
                }
            }
        }
    }

    // finalize
    l0 += __shfl_xor_sync(0xffffffffu, l0, 1);
    l0 += __shfl_xor_sync(0xffffffffu, l0, 2);
    l1 += __shfl_xor_sync(0xffffffffu, l1, 1);
    l1 += __shfl_xor_sync(0xffffffffu, l1, 2);
    const float inv0 = 1.0f / l0, inv1 = 1.0f / l1;

    const size_t rb0 = (size_t)(b*SS + c*WW + wrow + r4) * DD + h*DH;
    const size_t rb1 = rb0 + 8*DD;
    #pragma unroll
    for (int nf = 0; nf < 8; nf++) {
        const int col = nf*8 + t4*2;
        float2 o0, o1;
        o0.x = xin[rb0 + col]     + Of[nf][0] * inv0;
        o0.y = xin[rb0 + col + 1] + Of[nf][1] * inv0;
        o1.x = xin[rb1 + col]     + Of[nf][2] * inv1;
        o1.y = xin[rb1 + col + 1] + Of[nf][3] * inv1;
        *(float2*)(xout + rb0 + col) = o0;
        *(float2*)(xout + rb1 + col) = o1;
        *(__half2*)(xh + rb0 + col) = __floats2half2_rn(o0.x, o0.y);
        *(__half2*)(xh + rb1 + col) = __floats2half2_rn(o1.x, o1.y);
    }
}

// ---------------- fused add + LayerNorm (dual fp32/fp16 output) ----------------
__device__ __forceinline__ float block_sum_256(float v, float* red) {
    int lane = threadIdx.x & 31;
    #pragma unroll
    for (int o = 16; o > 0; o >>= 1) v += __shfl_xor_sync(0xffffffffu, v, o);
    if (lane == 0) red[threadIdx.x >> 5] = v;
    __syncthreads();
    float r = (threadIdx.x < 8) ? red[threadIdx.x] : 0.f;
    if ((threadIdx.x >> 5) == 0) {
        #pragma unroll
        for (int o = 16; o > 0; o >>= 1) r += __shfl_xor_sync(0xffffffffu, r, o);
        if (lane == 0) red[0] = r;
    }
    __syncthreads();
    r = red[0];
    __syncthreads();
    return r;
}

__global__ __launch_bounds__(256) void add_ln_kernel(
    const float* __restrict__ x, const float* __restrict__ hh,
    const float* __restrict__ hh2,
    const float* __restrict__ g, const float* __restrict__ bta,
    float* __restrict__ out, __half* __restrict__ outh)
{
    __shared__ float red[8];
    const int row = blockIdx.x;
    const size_t base = (size_t)row * DD;
    const int t = threadIdx.x;

    float vals[3];
    float s = 0.f;
    #pragma unroll
    for (int i = 0; i < 3; i++) {
        int idx = t + i * 256;
        float vv = x[base + idx];
        if (hh)  vv += hh[base + idx];
        if (hh2) vv += hh2[base + idx];
        vals[i] = vv;
        s += vv;
    }
    float total = block_sum_256(s, red);
    float mu = total * (1.0f / DD);

    float vsum = 0.f;
    #pragma unroll
    for (int i = 0; i < 3; i++) {
        float d = vals[i] - mu;
        vsum += d * d;
    }
    float vtot = block_sum_256(vsum, red);
    float rstd = rsqrtf(vtot * (1.0f / DD) + 1e-6f);

    #pragma unroll
    for (int i = 0; i < 3; i++) {
        int idx = t + i * 256;
        float o = (vals[i] - mu) * rstd * g[idx] + bta[idx];
        out[base + idx] = o;
        if (outh) outh[base + idx] = __float2half(o);
    }
}

// ---------------- launcher ----------------
extern "C" void kernel_launch(void* const* d_in, const int* in_sizes, int n_in,
                              void* d_out, int out_size)
{
    const float* src   = (const float*)d_in[0];
    const float* Wq    = (const float*)d_in[1];
    const float* bq    = (const float*)d_in[2];
    const float* Wk    = (const float*)d_in[3];
    const float* bk    = (const float*)d_in[4];
    const float* Wv    = (const float*)d_in[5];
    const float* bv    = (const float*)d_in[6];
    const float* W1    = (const float*)d_in[7];
    const float* b1    = (const float*)d_in[8];
    const float* W2    = (const float*)d_in[9];
    const float* b2    = (const float*)d_in[10];
    const float* ln2_g = (const float*)d_in[11];
    const float* ln2_b = (const float*)d_in[12];
    const float* lnf_g = (const float*)d_in[13];
    const float* lnf_b = (const float*)d_in[14];

    float *x, *h2, *h2b, *zb;
    __half *xh, *qh, *kh, *vh, *h1, *wq, *wk, *wv, *w1, *w2;
    cudaGetSymbolAddress((void**)&x,   g_x);
    cudaGetSymbolAddress((void**)&xh,  g_xh);
    cudaGetSymbolAddress((void**)&qh,  g_qh);
    cudaGetSymbolAddress((void**)&kh,  g_kh);
    cudaGetSymbolAddress((void**)&vh,  g_vh);
    cudaGetSymbolAddress((void**)&h1,  g_h1);
    cudaGetSymbolAddress((void**)&h2,  g_h2);
    cudaGetSymbolAddress((void**)&h2b, g_h2b);
    cudaGetSymbolAddress((void**)&zb,  g_zero);
    cudaGetSymbolAddress((void**)&wq,  g_wq);
    cudaGetSymbolAddress((void**)&wk,  g_wk);
    cudaGetSymbolAddress((void**)&wv,  g_wv);
    cudaGetSymbolAddress((void**)&w1,  g_w1);
    cudaGetSymbolAddress((void**)&w2,  g_w2);

    cudaFuncSetAttribute(band_attn_tc,
                         cudaFuncAttributeMaxDynamicSharedMemorySize, ATTN_SMEM);
    cudaFuncSetAttribute(gemm_f16<true,true>,
                         cudaFuncAttributeMaxDynamicSharedMemorySize, GEMM_SMEM);
    cudaFuncSetAttribute(gemm_f16<false,false>,
                         cudaFuncAttributeMaxDynamicSharedMemorySize, GEMM_SMEM);
    cudaFuncSetAttribute(gemm_ffn2_sk,
                         cudaFuncAttributeMaxDynamicSharedMemorySize, GEMM_SMEM);
    cudaFuncSetAttribute(gemm_qkv,
                         cudaFuncAttributeMaxDynamicSharedMemorySize, GEMM_SMEM);

    // weight transpose+convert to fp16 [N][K], batched over layers
    {
        dim3 blk(256);
        trans_f16_kernel<<<dim3(DD/32, DD/64, LL), blk>>>(Wq, wq, DD, DD);
        trans_f16_kernel<<<dim3(DD/32, DD/64, LL), blk>>>(Wk, wk, DD, DD);
        trans_f16_kernel<<<dim3(DD/32, DD/64, LL), blk>>>(Wv, wv, DD, DD);
        trans_f16_kernel<<<dim3(DFF/32, DD/64, LL), blk>>>(W1, w1, DD, DFF);
        trans_f16_kernel<<<dim3(DD/32, DFF/64, LL), blk>>>(W2, w2, DFF, DD);
    }

    // src -> fp16 for layer-0 QKV
    f32_to_f16_kernel<<<(MM*DD/4 + 255)/256, 256>>>(src, xh, MM*DD/4);

    dim3 gQKV(18, MM/128);          // 3 x (768/128) n-tiles
    dim3 gF1(DFF/128, MM/128);      // (24, 64)
    dim3 gF2(DD/128, MM/128, 2);    // (6, 64, 2) split-K: 768 CTAs
    dim3 gA(NC, HH, BB);

    for (int i = 0; i < LL; i++) {
        const float* xin = (i == 0) ? src : x;

        gemm_qkv<<<gQKV, 128, GEMM_SMEM>>>(xh,
            wq + (size_t)i*DD*DD, wk + (size_t)i*DD*DD, wv + (size_t)i*DD*DD,
            bq + i*DD, bk + i*DD, bv + i*DD, qh, kh, vh);

        band_attn_tc<<<gA, 256, ATTN_SMEM>>>(qh, kh, vh, xin, x, xh);

        gemm_f16<true,true><<<gF1, 128, GEMM_SMEM>>>(
            xh, w1 + (size_t)i*DD*DFF, b1 + i*DFF, nullptr, h1, DFF, DD);
        gemm_ffn2_sk<<<gF2, 128, GEMM_SMEM>>>(
            h1, w2 + (size_t)i*DFF*DD, b2 + i*DD, zb, h2, h2b);

        add_ln_kernel<<<MM, 256>>>(x, h2, h2b, ln2_g + i*DD, ln2_b + i*DD, x, xh);
    }

    add_ln_kernel<<<MM, 256>>>(x, nullptr, nullptr, lnf_g, lnf_b, (float*)d_out, nullptr);
}

// round 16
// speedup vs baseline: 1.5402x; 1.0102x over previous
#include <cuda_runtime.h>
#include <cuda_fp16.h>
#include <math.h>
#include <stdint.h>

// Problem constants
#define BB 2
#define SS 4096
#define DD 768
#define HH 12
#define LL 4
#define WW 128
#define DFF 3072
#define DH 64
#define MM (BB*SS)          // 8192 rows
#define NC (SS/WW)          // 32 chunks

#define NEG_BIG (-1e30f)
#define M_CLAMP (-1e28f)

// ---------------- scratch buffers ----------------
__device__ float  g_x [MM*DD];
__device__ __half g_xh[MM*DD];           // fp16 activation stream (GEMM A)
__device__ __half g_qh[MM*DD];           // fp16 q (pre-scaled by 1/8), k, v
__device__ __half g_kh[MM*DD];
__device__ __half g_vh[MM*DD];
__device__ __half g_h1[MM*DFF];          // FFN intermediate, fp16
__device__ float  g_h2 [MM*DD];          // FFN2 split-K partial 0 (+bias)
__device__ float  g_h2b[MM*DD];          // FFN2 split-K partial 1
__device__ float  g_zero[DD];            // zero bias (static-zeroed)
// fp16 weights, transposed to [N][K]
__device__ __half g_wq[LL*DD*DD];
__device__ __half g_wk[LL*DD*DD];
__device__ __half g_wv[LL*DD*DD];
__device__ __half g_w1[LL*DD*DFF];
__device__ __half g_w2[LL*DFF*DD];

// ---------------- helpers ----------------
__device__ __forceinline__ uint32_t smem_u32(const void* p) {
    uint32_t a;
    asm("{ .reg .u64 t; cvta.to.shared.u64 t, %1; cvt.u32.u64 %0, t; }"
        : "=r"(a) : "l"(p));
    return a;
}
__device__ __forceinline__ void cp16(uint32_t s, const void* g) {
    asm volatile("cp.async.cg.shared.global [%0], [%1], 16;" :: "r"(s), "l"(g));
}
__device__ __forceinline__ void mma16n8k16(float* c, const uint32_t* a, const uint32_t* b) {
    asm volatile(
        "mma.sync.aligned.m16n8k16.row.col.f32.f16.f16.f32 "
        "{%0,%1,%2,%3}, {%4,%5,%6,%7}, {%8,%9}, {%0,%1,%2,%3};"
        : "+f"(c[0]), "+f"(c[1]), "+f"(c[2]), "+f"(c[3])
        : "r"(a[0]), "r"(a[1]), "r"(a[2]), "r"(a[3]), "r"(b[0]), "r"(b[1]));
}
__device__ __forceinline__ void ldsm_x4(uint32_t* r, uint32_t addr) {
    asm volatile("ldmatrix.sync.aligned.m8n8.x4.shared.b16 {%0,%1,%2,%3}, [%4];"
        : "=r"(r[0]), "=r"(r[1]), "=r"(r[2]), "=r"(r[3]) : "r"(addr));
}
__device__ __forceinline__ uint32_t h2pack(float a, float b) {
    __half2 h = __floats2half2_rn(a, b);
    return *(uint32_t*)&h;
}

// ---------------- conversion passes ----------------
__global__ __launch_bounds__(256) void f32_to_f16_kernel(
    const float* __restrict__ in, __half* __restrict__ out, int n4)
{
    int i = blockIdx.x * 256 + threadIdx.x;
    if (i < n4) {
        float4 v = ((const float4*)in)[i];
        ((__half2*)out)[i*2]   = __floats2half2_rn(v.x, v.y);
        ((__half2*)out)[i*2+1] = __floats2half2_rn(v.z, v.w);
    }
}

// transpose + convert: in f32 [R][C] -> out f16 [C][R], batched over layers (z).
__global__ __launch_bounds__(256) void trans_f16_kernel(
    const float* __restrict__ in, __half* __restrict__ out, int R, int C)
{
    __shared__ float t[64][33];
    const size_t lo = (size_t)blockIdx.z * R * C;
    const int bx = blockIdx.x * 32;
    const int by = blockIdx.y * 64;
    const int tx = threadIdx.x & 31;
    const int ty = threadIdx.x >> 5;
    #pragma unroll
    for (int i = ty; i < 64; i += 8)
        t[i][tx] = in[lo + (size_t)(by + i) * C + bx + tx];
    __syncthreads();
    #pragma unroll
    for (int r = ty; r < 32; r += 8) {
        __half2 h = __floats2half2_rn(t[2*tx][r], t[2*tx + 1][r]);
        *(__half2*)(out + lo + (size_t)(bx + r) * R + by + 2*tx) = h;
    }
}

// ---------------- fp16 mma GEMM: C = A(MxK) @ Bt(NxK)^T + bias ----------------
// CTA tile 128x128, 128 threads (4 warps, warp tile 64x64), K-chunk 32 halves,
// 4-stage cp.async, ldmatrix fragment loads, 2 CTAs/SM.
#define HPAD 40                     // halves per smem row (32 + 8)
#define A_STG (128*HPAD)
#define B_STG (128*HPAD)
#define NSTG 4
#define GEMM_SMEM (NSTG*(A_STG + B_STG)*2)   // 81920 B

template<bool RELU, bool OUTH>
__device__ __forceinline__ void gemm_body(
    const __half* __restrict__ A, const __half* __restrict__ Bt,
    const float* __restrict__ bias, float* __restrict__ Cf, __half* __restrict__ Ch,
    int N, int K, int cn0, int tm, __half* smh, float oscale)
{
    const int tid  = threadIdx.x;
    const int lane = tid & 31;
    const int wid  = tid >> 5;       // 0..3
    const int wm   = wid & 1;
    const int wn   = wid >> 1;       // 0..1
    const int r4   = lane >> 2;
    const int t4   = lane & 3;

    const uint32_t sbase = smem_u32(smh);
    const __half* aG[4]; uint32_t aS[4];
    const __half* bG[4]; uint32_t bS[4];
    #pragma unroll
    for (int i = 0; i < 4; i++) {
        int id = tid + i*128;
        int row = id >> 2, kc = id & 3;
        aG[i] = A + (size_t)(tm*128 + row) * K + kc*8;
        aS[i] = sbase + (uint32_t)(row*HPAD + kc*8) * 2u;
        bG[i] = Bt + (size_t)(cn0 + row) * K + kc*8;
        bS[i] = sbase + (uint32_t)(NSTG*A_STG)*2u + (uint32_t)(row*HPAD + kc*8) * 2u;
    }

    auto issue = [&](int s, int c) {
        const uint32_t ao = (uint32_t)s * (A_STG*2);
        const uint32_t bo = (uint32_t)s * (B_STG*2);
        #pragma unroll
        for (int i = 0; i < 4; i++) {
            cp16(aS[i] + ao, aG[i] + c*32);
            cp16(bS[i] + bo, bG[i] + c*32);
        }
    };

    const int a_lrow = lane & 15;
    const int a_lk   = (lane >> 4) * 8;
    const int b_lrow = (lane & 7) + ((lane >> 4) << 3);
    const int b_lk   = ((lane >> 3) & 1) * 8;

    float acc[4][8][4];
    #pragma unroll
    for (int i = 0; i < 4; i++)
        #pragma unroll
        for (int j = 0; j < 8; j++)
            #pragma unroll
            for (int t = 0; t < 4; t++) acc[i][j][t] = 0.f;

    const int NCH = K >> 5;
    issue(0, 0); asm volatile("cp.async.commit_group;");
    issue(1, 1); asm volatile("cp.async.commit_group;");
    issue(2, 2); asm volatile("cp.async.commit_group;");

    for (int c = 0; c < NCH; c++) {
        asm volatile("cp.async.wait_group 2;");
        __syncthreads();
        if (c + 3 < NCH) issue((c + 3) & 3, c + 3);
        asm volatile("cp.async.commit_group;");

        const uint32_t as = sbase + (uint32_t)(c & 3) * (A_STG*2);
        const uint32_t bs = sbase + (uint32_t)(NSTG*A_STG)*2u + (uint32_t)(c & 3) * (B_STG*2);
        #pragma unroll
        for (int ks = 0; ks < 2; ks++) {
            const int k0 = ks * 16;
            uint32_t af[4][4], bf[8][2];
            #pragma unroll
            for (int mi = 0; mi < 4; mi++)
                ldsm_x4(af[mi], as + (uint32_t)((wm*64 + mi*16 + a_lrow)*HPAD + k0 + a_lk) * 2u);
            #pragma unroll
            for (int np = 0; np < 4; np++) {
                uint32_t t[4];
                ldsm_x4(t, bs + (uint32_t)((wn*64 + np*16 + b_lrow)*HPAD + k0 + b_lk) * 2u);
                bf[2*np][0] = t[0]; bf[2*np][1] = t[1];
                bf[2*np+1][0] = t[2]; bf[2*np+1][1] = t[3];
            }
            #pragma unroll
            for (int mi = 0; mi < 4; mi++)
                #pragma unroll
                for (int ni = 0; ni < 8; ni++)
                    mma16n8k16(acc[mi][ni], af[mi], bf[ni]);
        }
    }

    #pragma unroll
    for (int mi = 0; mi < 4; mi++) {
        const int row0 = tm*128 + wm*64 + mi*16 + r4;
        #pragma unroll
        for (int ni = 0; ni < 8; ni++) {
            const int col = cn0 + wn*64 + ni*8 + t4*2;
            const float b0 = bias[col], b1 = bias[col + 1];
            float2 v0, v1;
            v0.x = acc[mi][ni][0] + b0; v0.y = acc[mi][ni][1] + b1;
            v1.x = acc[mi][ni][2] + b0; v1.y = acc[mi][ni][3] + b1;
            if (RELU) {
                v0.x = fmaxf(v0.x, 0.f); v0.y = fmaxf(v0.y, 0.f);
                v1.x = fmaxf(v1.x, 0.f); v1.y = fmaxf(v1.y, 0.f);
            }
            if (OUTH) {
                v0.x *= oscale; v0.y *= oscale; v1.x *= oscale; v1.y *= oscale;
                *(__half2*)(Ch + (size_t)row0 * N + col)       = __floats2half2_rn(v0.x, v0.y);
                *(__half2*)(Ch + (size_t)(row0 + 8) * N + col) = __floats2half2_rn(v1.x, v1.y);
            } else {
                *(float2*)(Cf + (size_t)row0 * N + col)       = v0;
                *(float2*)(Cf + (size_t)(row0 + 8) * N + col) = v1;
            }
        }
    }
}

template<bool RELU, bool OUTH>
__global__ __launch_bounds__(128, 2) void gemm_f16(
    const __half* __restrict__ A, const __half* __restrict__ Bt,
    const float* __restrict__ bias, float* __restrict__ Cf, __half* __restrict__ Ch,
    int N, int K)
{
    extern __shared__ __half smh[];
    gemm_body<RELU, OUTH>(A, Bt, bias, Cf, Ch, N, K, blockIdx.x * 128, blockIdx.y, smh, 1.0f);
}

__global__ __launch_bounds__(128, 2) void gemm_qkv(
    const __half* __restrict__ A,
    const __half* __restrict__ Bq, const __half* __restrict__ Bk, const __half* __restrict__ Bv,
    const float* __restrict__ biq, const float* __restrict__ bik, const float* __restrict__ biv,
    __half* __restrict__ Cq, __half* __restrict__ Ck, __half* __restrict__ Cv)
{
    extern __shared__ __half smh[];
    const int sel = blockIdx.x / 6;
    const int tn  = blockIdx.x % 6;
    const __half* B  = (sel == 0) ? Bq  : (sel == 1) ? Bk  : Bv;
    const float*  bi = (sel == 0) ? biq : (sel == 1) ? bik : biv;
    __half*       C  = (sel == 0) ? Cq  : (sel == 1) ? Ck  : Cv;
    const float   sc = (sel == 0) ? 0.125f : 1.0f;
    gemm_body<false, true>(A, B, bi, nullptr, C, DD, DD, tn * 128, blockIdx.y, smh, sc);
}

// ---------------- FFN2 split-K: dedicated body, all constants compile-time ----------
__device__ __forceinline__ void gemm_body_sk(
    const __half* __restrict__ A, const __half* __restrict__ Bt,
    const float* __restrict__ bias, float* __restrict__ Cf,
    int cn0, int tm, __half* smh)
{
    constexpr int KLEN = DFF / 2;    // 1536
    constexpr int LD   = DFF;        // 3072
    constexpr int N    = DD;         // 768

    const int tid  = threadIdx.x;
    const int lane = tid & 31;
    const int wid  = tid >> 5;
    const int wm   = wid & 1;
    const int wn   = wid >> 1;
    const int r4   = lane >> 2;
    const int t4   = lane & 3;

    const uint32_t sbase = smem_u32(smh);
    const __half* aG[4]; uint32_t aS[4];
    const __half* bG[4]; uint32_t bS[4];
    #pragma unroll
    for (int i = 0; i < 4; i++) {
        int id = tid + i*128;
        int row = id >> 2, kc = id & 3;
        aG[i] = A + (size_t)(tm*128 + row) * LD + kc*8;
        aS[i] = sbase + (uint32_t)(row*HPAD + kc*8) * 2u;
        bG[i] = Bt + (size_t)(cn0 + row) * LD + kc*8;
        bS[i] = sbase + (uint32_t)(NSTG*A_STG)*2u + (uint32_t)(row*HPAD + kc*8) * 2u;
    }

    auto issue = [&](int s, int c) {
        const uint32_t ao = (uint32_t)s * (A_STG*2);
        const uint32_t bo = (uint32_t)s * (B_STG*2);
        #pragma unroll
        for (int i = 0; i < 4; i++) {
            cp16(aS[i] + ao, aG[i] + c*32);
            cp16(bS[i] + bo, bG[i] + c*32);
        }
    };

    const int a_lrow = lane & 15;
    const int a_lk   = (lane >> 4) * 8;
    const int b_lrow = (lane & 7) + ((lane >> 4) << 3);
    const int b_lk   = ((lane >> 3) & 1) * 8;

    float acc[4][8][4];
    #pragma unroll
    for (int i = 0; i < 4; i++)
        #pragma unroll
        for (int j = 0; j < 8; j++)
            #pragma unroll
            for (int t = 0; t < 4; t++) acc[i][j][t] = 0.f;

    constexpr int NCH = KLEN >> 5;   // 48
    issue(0, 0); asm volatile("cp.async.commit_group;");
    issue(1, 1); asm volatile("cp.async.commit_group;");
    issue(2, 2); asm volatile("cp.async.commit_group;");

    for (int c = 0; c < NCH; c++) {
        asm volatile("cp.async.wait_group 2;");
        __syncthreads();
        if (c + 3 < NCH) issue((c + 3) & 3, c + 3);
        asm volatile("cp.async.commit_group;");

        const uint32_t as = sbase + (uint32_t)(c & 3) * (A_STG*2);
        const uint32_t bs = sbase + (uint32_t)(NSTG*A_STG)*2u + (uint32_t)(c & 3) * (B_STG*2);
        #pragma unroll
        for (int ks = 0; ks < 2; ks++) {
            const int k0 = ks * 16;
            uint32_t af[4][4], bf[8][2];
            #pragma unroll
            for (int mi = 0; mi < 4; mi++)
                ldsm_x4(af[mi], as + (uint32_t)((wm*64 + mi*16 + a_lrow)*HPAD + k0 + a_lk) * 2u);
            #pragma unroll
            for (int np = 0; np < 4; np++) {
                uint32_t t[4];
                ldsm_x4(t, bs + (uint32_t)((wn*64 + np*16 + b_lrow)*HPAD + k0 + b_lk) * 2u);
                bf[2*np][0] = t[0]; bf[2*np][1] = t[1];
                bf[2*np+1][0] = t[2]; bf[2*np+1][1] = t[3];
            }
            #pragma unroll
            for (int mi = 0; mi < 4; mi++)
                #pragma unroll
                for (int ni = 0; ni < 8; ni++)
                    mma16n8k16(acc[mi][ni], af[mi], bf[ni]);
        }
    }

    #pragma unroll
    for (int mi = 0; mi < 4; mi++) {
        const int row0 = tm*128 + wm*64 + mi*16 + r4;
        #pragma unroll
        for (int ni = 0; ni < 8; ni++) {
            const int col = cn0 + wn*64 + ni*8 + t4*2;
            const float b0 = bias[col], b1 = bias[col + 1];
            float2 v0, v1;
            v0.x = acc[mi][ni][0] + b0; v0.y = acc[mi][ni][1] + b1;
            v1.x = acc[mi][ni][2] + b0; v1.y = acc[mi][ni][3] + b1;
            *(float2*)(Cf + (size_t)row0 * N + col)       = v0;
            *(float2*)(Cf + (size_t)(row0 + 8) * N + col) = v1;
        }
    }
}

__global__ __launch_bounds__(128, 2) void gemm_ffn2_sk(
    const __half* __restrict__ A, const __half* __restrict__ Bt,
    const float* __restrict__ bias, const float* __restrict__ zbias,
    float* __restrict__ C0, float* __restrict__ C1)
{
    extern __shared__ __half smh[];
    const int z = blockIdx.z;
    gemm_body_sk(A + z * (DFF/2), Bt + z * (DFF/2),
                 z ? zbias : bias, z ? C1 : C0,
                 blockIdx.x * 128, blockIdx.y, smh);
}

// ---------------- tensor-core band attention (round-11 verified) ----------------
#define QP 72                       // halves per qs/ks row (64 + 8)
#define VP 136                      // halves per vt row (128 + 8)
#define ATTN_SMEM ((2*128*QP + 64*VP)*2)   // 54272 B

__global__ __launch_bounds__(256, 2) void band_attn_tc(
    const __half* __restrict__ q, const __half* __restrict__ k,
    const __half* __restrict__ v, const float* __restrict__ xin,
    float* __restrict__ xout, __half* __restrict__ xh)
{
    extern __shared__ __half sm[];
    __half* qs = sm;                  // 128 x QP
    __half* ks = sm + 128*QP;         // 128 x QP
    __half* vt = sm + 2*128*QP;       // 64 x VP (transposed V)

    const int c = blockIdx.x, h = blockIdx.y, b = blockIdx.z;
    const int tid  = threadIdx.x;
    const int lane = tid & 31;
    const int w    = tid >> 5;
    const int r4   = lane >> 2, t4 = lane & 3;
    const int wrow = w * 16;

    const uint32_t qsu = smem_u32(qs);
    const uint32_t ksu = smem_u32(ks);
    const uint32_t vtu = smem_u32(vt);

    const int a_lrow = lane & 15;
    const int a_lk   = (lane >> 4) * 8;
    const int b_lrow = (lane & 7) + ((lane >> 4) << 3);
    const int b_lk   = ((lane >> 3) & 1) * 8;

    // Q tile
    {
        const int row = tid >> 1, ch = (tid & 1) * 4;
        const __half* gq = q + (size_t)(b*SS + c*WW + row) * DD + h*DH + ch*8;
        const uint32_t ds = qsu + (uint32_t)(row*QP + ch*8) * 2u;
        #pragma unroll
        for (int i = 0; i < 4; i++) cp16(ds + i*16, gq + i*8);
    }
    asm volatile("cp.async.commit_group;");

    float Of[8][4];
    #pragma unroll
    for (int i = 0; i < 8; i++)
        #pragma unroll
        for (int j = 0; j < 4; j++) Of[i][j] = 0.f;
    float m0 = M_CLAMP, m1 = M_CLAMP, l0 = 0.f, l1 = 0.f;
    uint32_t qa[4][4];

    const int tbeg = (c == 0) ? 1 : 0;
    const int tend = (c == NC-1) ? 1 : 2;

    for (int t = tbeg; t <= tend; t++) {
        __syncthreads();
        // K tile
        {
            const int row = tid >> 1, ch = (tid & 1) * 4;
            const int jg = c*WW + t*128 - WW + row;
            const __half* gk = k + (size_t)(b*SS + jg) * DD + h*DH + ch*8;
            const uint32_t ds = ksu + (uint32_t)(row*QP + ch*8) * 2u;
            #pragma unroll
            for (int i = 0; i < 4; i++) cp16(ds + i*16, gk + i*8);
        }
        asm volatile("cp.async.commit_group;");
        // V tile -> transposed into vt[dim][key]
        {
            const int key = tid >> 1, d0 = (tid & 1) * 32;
            const int jg = c*WW + t*128 - WW + key;
            const __half* gv = v + (size_t)(b*SS + jg) * DD + h*DH + d0;
            #pragma unroll
            for (int i = 0; i < 4; i++) {
                uint4 u = *(const uint4*)(gv + i*8);
                const __half* hp = (const __half*)&u;
                #pragma unroll
                for (int d = 0; d < 8; d++)
                    vt[(d0 + i*8 + d)*VP + key] = hp[d];
            }
        }
        asm volatile("cp.async.wait_group 0;");
        __syncthreads();

        if (t == tbeg) {   // Q fragments, loaded once
            #pragma unroll
            for (int kk = 0; kk < 4; kk++)
                ldsm_x4(qa[kk], qsu + (uint32_t)((wrow + a_lrow)*QP + kk*16 + a_lk) * 2u);
        }

        // two halves of 64 keys each: chunked online softmax (S = 8 frags)
        #pragma unroll
        for (int half = 0; half < 2; half++) {
            const int kbase = half * 64;
            float S[8][4];
            #pragma unroll
            for (int j2 = 0; j2 < 4; j2++) {
                float* s0 = S[2*j2];
                float* s1 = S[2*j2+1];
                s0[0]=s0[1]=s0[2]=s0[3]=0.f;
                s1[0]=s1[1]=s1[2]=s1[3]=0.f;
                #pragma unroll
                for (int kk = 0; kk < 4; kk++) {
                    uint32_t bt[4];
                    ldsm_x4(bt, ksu + (uint32_t)((kbase + j2*16 + b_lrow)*QP + kk*16 + b_lk) * 2u);
                    mma16n8k16(s0, qa[kk], bt);
                    mma16n8k16(s1, qa[kk], bt + 2);
                }
            }

            // band mask
            if (t == 0) {
                #pragma unroll
                for (int j = 0; j < 8; j++) {
                    const int key0 = kbase + j*8 + t4*2;
                    const int q0 = wrow + r4, q1 = q0 + 8;
                    if (key0     < q0) S[j][0] = NEG_BIG;
                    if (key0 + 1 < q0) S[j][1] = NEG_BIG;
                    if (key0     < q1) S[j][2] = NEG_BIG;
                    if (key0 + 1 < q1) S[j][3] = NEG_BIG;
                }
            } else if (t == 2) {
                #pragma unroll
                for (int j = 0; j < 8; j++) {
                    const int key0 = kbase + j*8 + t4*2;
                    const int q0 = wrow + r4, q1 = q0 + 8;
                    if (key0     > q0) S[j][0] = NEG_BIG;
                    if (key0 + 1 > q0) S[j][1] = NEG_BIG;
                    if (key0     > q1) S[j][2] = NEG_BIG;
                    if (key0 + 1 > q1) S[j][3] = NEG_BIG;
                }
            }

            // row max, quad reduce; clamp handles fully-masked halves
            float mx0 = NEG_BIG, mx1 = NEG_BIG;
            #pragma unroll
            for (int j = 0; j < 8; j++) {
                mx0 = fmaxf(mx0, fmaxf(S[j][0], S[j][1]));
                mx1 = fmaxf(mx1, fmaxf(S[j][2], S[j][3]));
            }
            mx0 = fmaxf(mx0, __shfl_xor_sync(0xffffffffu, mx0, 1));
            mx0 = fmaxf(mx0, __shfl_xor_sync(0xffffffffu, mx0, 2));
            mx1 = fmaxf(mx1, __shfl_xor_sync(0xffffffffu, mx1, 1));
            mx1 = fmaxf(mx1, __shfl_xor_sync(0xffffffffu, mx1, 2));

            const float mn0 = fmaxf(fmaxf(m0, mx0), M_CLAMP);
            const float mn1 = fmaxf(fmaxf(m1, mx1), M_CLAMP);
            const float sc0 = __expf(m0 - mn0), sc1 = __expf(m1 - mn1);
            m0 = mn0; m1 = mn1;
            l0 *= sc0; l1 *= sc1;
            #pragma unroll
            for (int nf = 0; nf < 8; nf++) {
                Of[nf][0] *= sc0; Of[nf][1] *= sc0;
                Of[nf][2] *= sc1; Of[nf][3] *= sc1;
            }

            // exp -> P frags, then P @ V
            #pragma unroll
            for (int kk = 0; kk < 4; kk++) {
                const float p00 = __expf(S[2*kk][0]   - m0);
                const float p01 = __expf(S[2*kk][1]   - m0);
                const float p02 = __expf(S[2*kk][2]   - m1);
                const float p03 = __expf(S[2*kk][3]   - m1);
                const float p10 = __expf(S[2*kk+1][0] - m0);
                const float p11 = __expf(S[2*kk+1][1] - m0);
                const float p12 = __expf(S[2*kk+1][2] - m1);
                const float p13 = __expf(S[2*kk+1][3] - m1);
                l0 += p00 + p01 + p10 + p11;
                l1 += p02 + p03 + p12 + p13;
                uint32_t pa[4];
                pa[0] = h2pack(p00, p01);
                pa[1] = h2pack(p02, p03);
                pa[2] = h2pack(p10, p11);
                pa[3] = h2pack(p12, p13);
                #pragma unroll
                for (int np = 0; np < 4; np++) {
                    uint32_t bt[4];
                    ldsm_x4(bt, vtu + (uint32_t)((np*16 + b_lrow)*VP + kbase + kk*16 + b_lk) * 2u);
                    mma16n8k16(Of[2*np],   pa, bt);
                    mma16n8k16(Of[2*np+1], pa, bt + 2);
                }
            }
        }
    }

    // finalize
    l0 += __shfl_xor_sync(0xffffffffu, l0, 1);
    l0 += __shfl_xor_sync(0xffffffffu, l0, 2);
    l1 += __shfl_xor_sync(0xffffffffu, l1, 1);
    l1 += __shfl_xor_sync(0xffffffffu, l1, 2);
    const float inv0 = 1.0f / l0, inv1 = 1.0f / l1;

    const size_t rb0 = (size_t)(b*SS + c*WW + wrow + r4) * DD + h*DH;
    const size_t rb1 = rb0 + 8*DD;
    #pragma unroll
    for (int nf = 0; nf < 8; nf++) {
        const int col = nf*8 + t4*2;
        float2 o0, o1;
        o0.x = xin[rb0 + col]     + Of[nf][0] * inv0;
        o0.y = xin[rb0 + col + 1] + Of[nf][1] * inv0;
        o1.x = xin[rb1 + col]     + Of[nf][2] * inv1;
        o1.y = xin[rb1 + col + 1] + Of[nf][3] * inv1;
        *(float2*)(xout + rb0 + col) = o0;
        *(float2*)(xout + rb1 + col) = o1;
        *(__half2*)(xh + rb0 + col) = __floats2half2_rn(o0.x, o0.y);
        *(__half2*)(xh + rb1 + col) = __floats2half2_rn(o1.x, o1.y);
    }
}

// ---------------- fused add + LayerNorm (dual fp32/fp16 output) ----------------
__device__ __forceinline__ float block_sum_256(float v, float* red) {
    int lane = threadIdx.x & 31;
    #pragma unroll
    for (int o = 16; o > 0; o >>= 1) v += __shfl_xor_sync(0xffffffffu, v, o);
    if (lane == 0) red[threadIdx.x >> 5] = v;
    __syncthreads();
    float r = (threadIdx.x < 8) ? red[threadIdx.x] : 0.f;
    if ((threadIdx.x >> 5) == 0) {
        #pragma unroll
        for (int o = 16; o > 0; o >>= 1) r += __shfl_xor_sync(0xffffffffu, r, o);
        if (lane == 0) red[0] = r;
    }
    __syncthreads();
    r = red[0];
    __syncthreads();
    return r;
}

__global__ __launch_bounds__(256) void add_ln_kernel(
    const float* __restrict__ x, const float* __restrict__ hh,
    const float* __restrict__ hh2,
    const float* __restrict__ g, const float* __restrict__ bta,
    float* __restrict__ out, __half* __restrict__ outh)
{
    __shared__ float red[8];
    const int row = blockIdx.x;
    const size_t base = (size_t)row * DD;
    const int t = threadIdx.x;

    float vals[3];
    float s = 0.f;
    #pragma unroll
    for (int i = 0; i < 3; i++) {
        int idx = t + i * 256;
        float vv = x[base + idx];
        if (hh)  vv += hh[base + idx];
        if (hh2) vv += hh2[base + idx];
        vals[i] = vv;
        s += vv;
    }
    float total = block_sum_256(s, red);
    float mu = total * (1.0f / DD);

    float vsum = 0.f;
    #pragma unroll
    for (int i = 0; i < 3; i++) {
        float d = vals[i] - mu;
        vsum += d * d;
    }
    float vtot = block_sum_256(vsum, red);
    float rstd = rsqrtf(vtot * (1.0f / DD) + 1e-6f);

    #pragma unroll
    for (int i = 0; i < 3; i++) {
        int idx = t + i * 256;
        float o = (vals[i] - mu) * rstd * g[idx] + bta[idx];
        out[base + idx] = o;
        if (outh) outh[base + idx] = __float2half(o);
    }
}

// ---------------- launcher ----------------
extern "C" void kernel_launch(void* const* d_in, const int* in_sizes, int n_in,
                              void* d_out, int out_size)
{
    const float* src   = (const float*)d_in[0];
    const float* Wq    = (const float*)d_in[1];
    const float* bq    = (const float*)d_in[2];
    const float* Wk    = (const float*)d_in[3];
    const float* bk    = (const float*)d_in[4];
    const float* Wv    = (const float*)d_in[5];
    const float* bv    = (const float*)d_in[6];
    const float* W1    = (const float*)d_in[7];
    const float* b1    = (const float*)d_in[8];
    const float* W2    = (const float*)d_in[9];
    const float* b2    = (const float*)d_in[10];
    const float* ln2_g = (const float*)d_in[11];
    const float* ln2_b = (const float*)d_in[12];
    const float* lnf_g = (const float*)d_in[13];
    const float* lnf_b = (const float*)d_in[14];

    float *x, *h2, *h2b, *zb;
    __half *xh, *qh, *kh, *vh, *h1, *wq, *wk, *wv, *w1, *w2;
    cudaGetSymbolAddress((void**)&x,   g_x);
    cudaGetSymbolAddress((void**)&xh,  g_xh);
    cudaGetSymbolAddress((void**)&qh,  g_qh);
    cudaGetSymbolAddress((void**)&kh,  g_kh);
    cudaGetSymbolAddress((void**)&vh,  g_vh);
    cudaGetSymbolAddress((void**)&h1,  g_h1);
    cudaGetSymbolAddress((void**)&h2,  g_h2);
    cudaGetSymbolAddress((void**)&h2b, g_h2b);
    cudaGetSymbolAddress((void**)&zb,  g_zero);
    cudaGetSymbolAddress((void**)&wq,  g_wq);
    cudaGetSymbolAddress((void**)&wk,  g_wk);
    cudaGetSymbolAddress((void**)&wv,  g_wv);
    cudaGetSymbolAddress((void**)&w1,  g_w1);
    cudaGetSymbolAddress((void**)&w2,  g_w2);

    cudaFuncSetAttribute(band_attn_tc,
                         cudaFuncAttributeMaxDynamicSharedMemorySize, ATTN_SMEM);
    cudaFuncSetAttribute(gemm_f16<true,true>,
                         cudaFuncAttributeMaxDynamicSharedMemorySize, GEMM_SMEM);
    cudaFuncSetAttribute(gemm_f16<false,false>,
                         cudaFuncAttributeMaxDynamicSharedMemorySize, GEMM_SMEM);
    cudaFuncSetAttribute(gemm_ffn2_sk,
                         cudaFuncAttributeMaxDynamicSharedMemorySize, GEMM_SMEM);
    cudaFuncSetAttribute(gemm_qkv,
                         cudaFuncAttributeMaxDynamicSharedMemorySize, GEMM_SMEM);

    // weight transpose+convert to fp16 [N][K], batched over layers
    {
        dim3 blk(256);
        trans_f16_kernel<<<dim3(DD/32, DD/64, LL), blk>>>(Wq, wq, DD, DD);
        trans_f16_kernel<<<dim3(DD/32, DD/64, LL), blk>>>(Wk, wk, DD, DD);
        trans_f16_kernel<<<dim3(DD/32, DD/64, LL), blk>>>(Wv, wv, DD, DD);
        trans_f16_kernel<<<dim3(DFF/32, DD/64, LL), blk>>>(W1, w1, DD, DFF);
        trans_f16_kernel<<<dim3(DD/32, DFF/64, LL), blk>>>(W2, w2, DFF, DD);
    }

    // src -> fp16 for layer-0 QKV
    f32_to_f16_kernel<<<(MM*DD/4 + 255)/256, 256>>>(src, xh, MM*DD/4);

    dim3 gQKV(18, MM/128);          // 3 x (768/128) n-tiles
    dim3 gF1(DFF/128, MM/128);      // (24, 64)
    dim3 gF2(DD/128, MM/128, 2);    // (6, 64, 2) split-K: 768 CTAs
    dim3 gA(NC, HH, BB);

    for (int i = 0; i < LL; i++) {
        const float* xin = (i == 0) ? src : x;

        gemm_qkv<<<gQKV, 128, GEMM_SMEM>>>(xh,
            wq + (size_t)i*DD*DD, wk + (size_t)i*DD*DD, wv + (size_t)i*DD*DD,
            bq + i*DD, bk + i*DD, bv + i*DD, qh, kh, vh);

        band_attn_tc<<<gA, 256, ATTN_SMEM>>>(qh, kh, vh, xin, x, xh);

        gemm_f16<true,true><<<gF1, 128, GEMM_SMEM>>>(
            xh, w1 + (size_t)i*DD*DFF, b1 + i*DFF, nullptr, h1, DFF, DD);
        gemm_ffn2_sk<<<gF2, 128, GEMM_SMEM>>>(
            h1, w2 + (size_t)i*DFF*DD, b2 + i*DD, zb, h2, h2b);

        add_ln_kernel<<<MM, 256>>>(x, h2, h2b, ln2_g + i*DD, ln2_b + i*DD, x, xh);
    }

    add_ln_kernel<<<MM, 256>>>(x, nullptr, nullptr, lnf_g, lnf_b, (float*)d_out, nullptr);
}